// round 17
// baseline (speedup 1.0000x reference)
#include <cuda_runtime.h>
#include <math.h>

#define S_LEN 128
#define B_SZ  64
#define H_SZ  512
#define O_SZ  256
#define NMAX  8
#define NBLK  64    // 64 j-groups; each block interleaves BOTH batch-half pipelines

typedef unsigned long long u64;

// ---------------- device scratch (static; allocation is forbidden) ----------------
__device__ __align__(16) float g_preT[S_LEN * H_SZ * B_SZ];   // [t][j][b]
__device__ __align__(16) float g_accsT[S_LEN * H_SZ * B_SZ];  // [t][j][b]
__device__ __align__(16) float g_hbuf[3 * H_SZ * B_SZ];       // [buf][k][b]
__device__ __align__(16) float g_haltv[3 * 2 * 256 * 32];     // [buf][half][jg*4+sub][b=32]
__device__ unsigned g_flag[128 * 32];                         // [half*64+jg], 128B stride

__device__ __forceinline__ void ffma2(u64 &d, u64 a, u64 b) {
    asm("fma.rn.f32x2 %0, %1, %2, %0;" : "+l"(d) : "l"(a), "l"(b));
}
__device__ __forceinline__ u64 add2(u64 a, u64 b) {
    u64 r;
    asm("add.rn.f32x2 %0, %1, %2;" : "=l"(r) : "l"(a), "l"(b));
    return r;
}
__device__ __forceinline__ float lo32(u64 v) { return __uint_as_float((unsigned)(v & 0xffffffffu)); }
__device__ __forceinline__ float hi32(u64 v) { return __uint_as_float((unsigned)(v >> 32)); }
__device__ __forceinline__ u64 pack2(float x, float y) {
    return ((u64)__float_as_uint(y) << 32) | (u64)__float_as_uint(x);
}
__device__ __forceinline__ unsigned ld_acq(unsigned* p) {
    unsigned v;
    asm volatile("ld.acquire.gpu.u32 %0, [%1];" : "=r"(v) : "l"(p) : "memory");
    return v;
}
__device__ __forceinline__ void st_rel(unsigned* p, unsigned v) {
    asm volatile("st.release.gpu.u32 [%0], %1;" :: "l"(p), "r"(v) : "memory");
}

// ---------------- kernel 1: pre-projection GEMM ----------------
__global__ void __launch_bounds__(256) pre_gemm(const float* __restrict__ x,
                                                const float* __restrict__ W_ih,
                                                const float* __restrict__ b_ih,
                                                const float* __restrict__ b_hh) {
    __shared__ float Xs[64 * 65];
    __shared__ float Ws[64 * 65];
    const int t = blockIdx.y, jt = blockIdx.x;
    const int tid = threadIdx.x;
    const int ty = tid >> 4, tx = tid & 15;
    float acc[4][4] = {};
    for (int kc = 0; kc < 4; ++kc) {
        __syncthreads();
        for (int i = tid; i < 4096; i += 256) {
            int r = i >> 6, kk = i & 63;
            Xs[r * 65 + kk] = x[(t * 64 + r) * 256 + kc * 64 + kk];
            Ws[r * 65 + kk] = W_ih[(jt * 64 + r) * 257 + 1 + kc * 64 + kk];
        }
        __syncthreads();
        #pragma unroll 8
        for (int kk = 0; kk < 64; ++kk) {
            float wv[4], xv[4];
            #pragma unroll
            for (int a = 0; a < 4; ++a) wv[a] = Ws[(ty * 4 + a) * 65 + kk];
            #pragma unroll
            for (int c = 0; c < 4; ++c) xv[c] = Xs[(tx * 4 + c) * 65 + kk];
            #pragma unroll
            for (int a = 0; a < 4; ++a)
                #pragma unroll
                for (int c = 0; c < 4; ++c)
                    acc[a][c] = fmaf(wv[a], xv[c], acc[a][c]);
        }
    }
    #pragma unroll
    for (int a = 0; a < 4; ++a) {
        int j = jt * 64 + ty * 4 + a;
        float bias = b_ih[j] + b_hh[j];
        #pragma unroll
        for (int c = 0; c < 4; ++c) {
            int b = tx * 4 + c;
            g_preT[(t * 512 + j) * 64 + b] = acc[a][c] + bias;
        }
    }
}

// ---------------- init: s -> buf0 [k][b]; reset all 128 flags ----------------
__global__ void init_h(const float* __restrict__ s) {
    if (threadIdx.x < 2) g_flag[(blockIdx.x * 2 + threadIdx.x) * 32] = 0u;
    int b = blockIdx.x;
    int j = threadIdx.x;
    g_hbuf[j * 64 + b] = s[b * 512 + j];
}

// ---------------- one step of one half-pipeline (R16 body, parameterized) ----------------
// Returns 1 when this half reaches t == S_LEN (no further work).
__device__ __forceinline__ int half_step(
    const int half, const int jg,
    const int tid, const int warp, const int lane,
    const int r4, const int q, const int jo, const int po, const int gjrow,
    unsigned &m, int &m3, int &nx3, int &t, int &n,
    float &cumx, float &cumy, int &hlx, int &hly, float &pondx, float &pondy,
    u64 (&accs)[32],
    const u64* sh_W2, u64* sh_part, float* sh_hp,
    const float* sh_whalt, const float* sh_wih0, const float bhalt,
    float* pond_out)
{
    const int b0 = (half << 5) + (po << 1);
    unsigned* myflag = &g_flag[((half << 6) + (warp << 3) + (lane < 8 ? lane : 0)) << 5];
    // ---- wait for this half's 64 producers ----
    for (;;) {
        unsigned v = (lane < 8) ? ld_acq(myflag) : 0xffffffffu;
        if (__all_sync(0xffffffffu, v >= m)) break;
        __nanosleep(32);
    }
    // ---- up-front h loads ----
    ulonglong2 h4[16];
    {
        const ulonglong2* bufv = (const ulonglong2*)((const u64*)g_hbuf + m3 * 16384);
        #pragma unroll
        for (int c = 0; c < 16; ++c)
            h4[c] = __ldcg(bufv + ((warp << 6) + (c << 2) + r4) * 16 + (half << 3) + q);
    }
    int allh = 0;
    if (n >= 1) {
        float2 hp2 = make_float2(0.f, 0.f);
        {
            const float2* hvr = (const float2*)(g_haltv + (m3 * 2 + half) * 8192);
            const int rbase = (warp << 5) + (lane >> 4);
            const int fi = lane & 15;
            #pragma unroll
            for (int i = 0; i < 16; ++i) {
                float2 v = __ldcg(hvr + (rbase + (i << 1)) * 16 + fi);
                hp2.x += v.x; hp2.y += v.y;
            }
            hp2.x += __shfl_xor_sync(0xffffffffu, hp2.x, 16);
            hp2.y += __shfl_xor_sync(0xffffffffu, hp2.y, 16);
        }
        if (lane < 16) *(float2*)(sh_hp + (warp << 5) + (lane << 1)) = hp2;
        __syncthreads();                                           // S1
        float sx = 0.f, sy = 0.f;
        #pragma unroll
        for (int w8 = 0; w8 < 8; ++w8) {
            float2 v = *(const float2*)(sh_hp + (w8 << 5) + (po << 1));
            sx += v.x; sy += v.y;
        }
        float px = 1.f / (1.f + expf(-(sx + bhalt)));
        float py = 1.f / (1.f + expf(-(sy + bhalt)));
        if (hlx) px = 0.f;
        if (hly) py = 0.f;
        int ihx = (!hlx) && (((cumx + px) >= 0.99f) || (n - 1 == NMAX - 1));
        int ihy = (!hly) && (((cumy + py) >= 0.99f) || (n - 1 == NMAX - 1));
        float wx = ihx ? (1.f - cumx) : px;
        float wy = ihy ? (1.f - cumy) : py;
        if (ihx) pondx = (1.f - cumx) + (float)n;
        if (ihy) pondy = (1.f - cumy) + (float)n;
        cumx += px; cumy += py;
        hlx |= ihx; hly |= ihy;
        allh = __all_sync(0xffffffffu, hlx && hly);
        float w0x = __shfl_sync(0xffffffffu, wx, (q << 1));
        float w0y = __shfl_sync(0xffffffffu, wy, (q << 1));
        float w1x = __shfl_sync(0xffffffffu, wx, (q << 1) + 1);
        float w1y = __shfl_sync(0xffffffffu, wy, (q << 1) + 1);
        u64 wp0 = pack2(w0x, w0y), wp1 = pack2(w1x, w1y);
        #pragma unroll
        for (int c = 0; c < 16; ++c) {
            ffma2(accs[2 * c],     h4[c].x, wp0);
            ffma2(accs[2 * c + 1], h4[c].y, wp1);
        }
    }
    int add_flag = (n == 0);
    if (allh) {
        if (jg == 0) {
            #pragma unroll
            for (int c = 0; c < 16; ++c) {
                int k = (warp << 6) + (c << 2) + r4;
                *(ulonglong2*)(g_accsT + ((t * 512 + k) << 6) + (half << 5) + (q << 2)) =
                    make_ulonglong2(accs[2 * c], accs[2 * c + 1]);
            }
            if (warp == 0 && lane < 16)
                *(float2*)(pond_out + t * 64 + (half << 5) + (po << 1)) =
                    make_float2(pondx, pondy);
        }
        cumx = cumy = 0.f; hlx = hly = 0; pondx = pondy = 0.f;
        #pragma unroll
        for (int c = 0; c < 16; ++c) {
            h4[c] = make_ulonglong2(accs[2 * c], accs[2 * c + 1]);
            accs[2 * c] = 0ull; accs[2 * c + 1] = 0ull;
        }
        ++t; n = 0; add_flag = 1;
        if (t == S_LEN) return 1;
    }
    // ---- GEMM on h4 ----
    u64 gac[8][2] = {};
    #pragma unroll
    for (int c = 0; c < 16; ++c) {
        const int k = (warp << 6) + (c << 2) + r4;
        ulonglong2 h2v = h4[c];
        const ulonglong2* wr = (const ulonglong2*)(sh_W2 + (k << 3));
        ulonglong2 w01 = wr[0], w23 = wr[1], w45 = wr[2], w67 = wr[3];
        ffma2(gac[0][0], h2v.x, w01.x); ffma2(gac[0][1], h2v.y, w01.x);
        ffma2(gac[1][0], h2v.x, w01.y); ffma2(gac[1][1], h2v.y, w01.y);
        ffma2(gac[2][0], h2v.x, w23.x); ffma2(gac[2][1], h2v.y, w23.x);
        ffma2(gac[3][0], h2v.x, w23.y); ffma2(gac[3][1], h2v.y, w23.y);
        ffma2(gac[4][0], h2v.x, w45.x); ffma2(gac[4][1], h2v.y, w45.x);
        ffma2(gac[5][0], h2v.x, w45.y); ffma2(gac[5][1], h2v.y, w45.y);
        ffma2(gac[6][0], h2v.x, w67.x); ffma2(gac[6][1], h2v.y, w67.x);
        ffma2(gac[7][0], h2v.x, w67.y); ffma2(gac[7][1], h2v.y, w67.y);
    }
    #pragma unroll
    for (int jj = 0; jj < 8; ++jj) {
        #pragma unroll
        for (int pp = 0; pp < 2; ++pp) {
            u64 v = gac[jj][pp];
            v = add2(v, __shfl_xor_sync(0xffffffffu, v, 8));
            v = add2(v, __shfl_xor_sync(0xffffffffu, v, 16));
            gac[jj][pp] = v;
        }
    }
    if (add_flag && n == 0 && t == 0) __syncthreads();  // one-time sh_part WAR guard
    if (lane < 8) {
        ulonglong2* pp = (ulonglong2*)(sh_part + (warp << 7));
        #pragma unroll
        for (int jj = 0; jj < 8; ++jj)
            pp[(jj << 3) + q] = make_ulonglong2(gac[jj][0], gac[jj][1]);
    }
    float2 pre2 = make_float2(0.f, 0.f);
    if (warp < 4)
        pre2 = __ldg((const float2*)(g_preT + ((t * 512 + gjrow) << 6) + b0));
    __syncthreads();                                               // S2
    if (warp < 4) {
        float sx = 0.f, sy = 0.f;
        #pragma unroll
        for (int g = 0; g < 8; ++g) {
            u64 v = sh_part[(g << 7) + (jo << 4) + po];
            sx += lo32(v); sy += hi32(v);
        }
        float ax = sx + pre2.x, ay = sy + pre2.y;
        if (add_flag) { float f = sh_wih0[jo]; ax += f; ay += f; }
        float hx = tanhf(ax), hyv = tanhf(ay);
        *((u64*)g_hbuf + nx3 * 16384 + gjrow * 32 + (half << 4) + po) = pack2(hx, hyv);
        float2 hw = make_float2(sh_whalt[jo] * hx, sh_whalt[jo] * hyv);
        hw.x += __shfl_xor_sync(0xffffffffu, hw.x, 16);
        hw.y += __shfl_xor_sync(0xffffffffu, hw.y, 16);
        if (lane < 16) {
            float2* hvw = (float2*)(g_haltv + (nx3 * 2 + half) * 8192);
            hvw[((jg << 2) + warp) * 16 + po] = hw;
        }
        if (half == 0) asm volatile("bar.sync 1, 128;" ::: "memory");
        else           asm volatile("bar.sync 2, 128;" ::: "memory");
        if (tid == 0) st_rel(&g_flag[((half << 6) + jg) << 5], m + 1);
    }
    ++n;
    ++m;
    m3 = nx3; nx3 = (nx3 + 1 == 3) ? 0 : nx3 + 1;
    return 0;
}

// ---------------- kernel 2: 64 blocks, both halves interleaved per block ----------------
__global__ void __launch_bounds__(256, 1) rnn_act(const float* __restrict__ W_hh,
                                                  const float* __restrict__ W_ih,
                                                  const float* __restrict__ W_halt,
                                                  const float* __restrict__ b_halt,
                                                  float* __restrict__ pond_out) {
    __shared__ __align__(16) u64   sh_W2[4096];    // [k=512][j=8] dup-pairs (32 KB)
    __shared__ __align__(16) u64   sh_part[1024];  // [grp=8][j=8][pair=16]     (8 KB)
    __shared__ __align__(16) float sh_hp[256];     // haltv partials [warp=8][b=32]
    __shared__ float sh_whalt[8];
    __shared__ float sh_wih0[8];
    __shared__ float sh_bhalt;

    const int jg   = blockIdx.x;
    const int tid  = threadIdx.x;
    const int warp = tid >> 5, lane = tid & 31;
    const int r4 = lane >> 3, q = lane & 7;
    const int jo = (warp << 1) + (lane >> 4);
    const int po = lane & 15;
    const int gjrow = jg * 8 + jo;

    for (int i = tid; i < 4096; i += 256) {
        int jj = i >> 9, k = i & 511;
        unsigned wb = __float_as_uint(W_hh[(jg * 8 + jj) * 512 + k]);
        sh_W2[k * 8 + jj] = ((u64)wb << 32) | (u64)wb;
    }
    if (tid < 8) {
        sh_whalt[tid] = W_halt[jg * 8 + tid];
        sh_wih0[tid]  = W_ih[(jg * 8 + tid) * 257];
    }
    if (tid == 0) sh_bhalt = b_halt[0];
    __syncthreads();
    const float bhalt = sh_bhalt;

    // per-half state machines
    unsigned mA = 0, mB = 0;
    int m3A = 0, nx3A = 1, tA = 0, nA = 0;
    int m3B = 0, nx3B = 1, tB = 0, nB = 0;
    float cumxA = 0.f, cumyA = 0.f, pondxA = 0.f, pondyA = 0.f;
    float cumxB = 0.f, cumyB = 0.f, pondxB = 0.f, pondyB = 0.f;
    int hlxA = 0, hlyA = 0, hlxB = 0, hlyB = 0;
    u64 accsA[32], accsB[32];
    #pragma unroll
    for (int i = 0; i < 32; ++i) { accsA[i] = 0ull; accsB[i] = 0ull; }

    int doneA = 0, doneB = 0;
    while (!doneA || !doneB) {
        if (!doneA)
            doneA = half_step(0, jg, tid, warp, lane, r4, q, jo, po, gjrow,
                              mA, m3A, nx3A, tA, nA,
                              cumxA, cumyA, hlxA, hlyA, pondxA, pondyA, accsA,
                              sh_W2, sh_part, sh_hp, sh_whalt, sh_wih0, bhalt, pond_out);
        if (!doneB)
            doneB = half_step(1, jg, tid, warp, lane, r4, q, jo, po, gjrow,
                              mB, m3B, nx3B, tB, nB,
                              cumxB, cumyB, hlxB, hlyB, pondxB, pondyB, accsB,
                              sh_W2, sh_part, sh_hp, sh_whalt, sh_wih0, bhalt, pond_out);
    }
}

// ---------------- kernel 3: output GEMM ----------------
__global__ void __launch_bounds__(256) out_gemm(const float* __restrict__ W_out,
                                                const float* __restrict__ b_out,
                                                float* __restrict__ out) {
    __shared__ float As[64 * 65];
    __shared__ float Ws[64 * 65];
    const int t = blockIdx.y, ot = blockIdx.x;
    const int tid = threadIdx.x;
    const int ty = tid >> 4, tx = tid & 15;
    float acc[4][4] = {};
    for (int kc = 0; kc < 8; ++kc) {
        __syncthreads();
        for (int i = tid; i < 4096; i += 256) {
            int r = i >> 6, c = i & 63;
            As[r * 65 + c] = g_accsT[(t * 512 + kc * 64 + r) * 64 + c];
            Ws[r * 65 + c] = W_out[(ot * 64 + r) * 512 + kc * 64 + c];
        }
        __syncthreads();
        #pragma unroll 8
        for (int kk = 0; kk < 64; ++kk) {
            float wv[4], xv[4];
            #pragma unroll
            for (int a = 0; a < 4; ++a) wv[a] = Ws[(ty * 4 + a) * 65 + kk];
            #pragma unroll
            for (int c = 0; c < 4; ++c) xv[c] = As[kk * 65 + tx * 4 + c];
            #pragma unroll
            for (int a = 0; a < 4; ++a)
                #pragma unroll
                for (int c = 0; c < 4; ++c)
                    acc[a][c] = fmaf(wv[a], xv[c], acc[a][c]);
        }
    }
    #pragma unroll
    for (int a = 0; a < 4; ++a) {
        int o = ot * 64 + ty * 4 + a;
        float bias = b_out[o];
        #pragma unroll
        for (int c = 0; c < 4; ++c) {
            int b = tx * 4 + c;
            out[(t * 64 + b) * 256 + o] = acc[a][c] + bias;
        }
    }
}

extern "C" void kernel_launch(void* const* d_in, const int* in_sizes, int n_in,
                              void* d_out, int out_size) {
    const float* x      = (const float*)d_in[0];
    const float* s      = (const float*)d_in[1];
    const float* W_ih   = (const float*)d_in[2];
    const float* b_ih   = (const float*)d_in[3];
    const float* W_hh   = (const float*)d_in[4];
    const float* b_hh   = (const float*)d_in[5];
    const float* W_out  = (const float*)d_in[6];
    const float* b_out  = (const float*)d_in[7];
    const float* W_halt = (const float*)d_in[8];
    const float* b_halt = (const float*)d_in[9];
    float* out  = (float*)d_out;                       // outputs [S,B,O]
    float* pond = out + S_LEN * B_SZ * O_SZ;           // ponder  [S,B]

    dim3 preg(8, S_LEN);
    pre_gemm<<<preg, 256>>>(x, W_ih, b_ih, b_hh);
    init_h<<<B_SZ, H_SZ>>>(s);
    rnn_act<<<NBLK, 256>>>(W_hh, W_ih, W_halt, b_halt, pond);
    dim3 outg(4, S_LEN);
    out_gemm<<<outg, 256>>>(W_out, b_out, out);
}